// round 4
// baseline (speedup 1.0000x reference)
#include <cuda_runtime.h>
#include <mma.h>
#include <math.h>

using namespace nvcuda;

// Problem constants
#define SQ   4096
#define EMB  768
#define NH   12
#define HD   64
#define WIN  256

// Scratch (allocation-free rule: __device__ globals)
__device__ float g_q[NH * SQ * HD];
__device__ float g_k[NH * SQ * HD];
__device__ float g_v[NH * SQ * HD];

// ---------------------------------------------------------------------------
// QKV projection with tf32 WMMA tensor cores.
// C = hs @ Wm + bm, scattered head-major into g_q/g_k/g_v.
// BM=128, BN=64, BK=32. 256 threads = 8 warps (4x2), warp tile 32x32.
// grid = (EMB/64, SQ/128, 3).
// ---------------------------------------------------------------------------
#define QKV_BM 128
#define QKV_BN 64
#define QKV_BK 32
#define AS_STRIDE 40   // 160B rows: 32B-aligned frag pointers
#define BS_STRIDE 72   // 288B rows
#define CS_STRIDE 72

__global__ __launch_bounds__(256) void qkv_kernel(
    const float* __restrict__ hs,
    const float* __restrict__ Wq, const float* __restrict__ bq,
    const float* __restrict__ Wk, const float* __restrict__ bk,
    const float* __restrict__ Wv, const float* __restrict__ bv)
{
    const int z = blockIdx.z;
    const float* Wm = (z == 0) ? Wq : (z == 1) ? Wk : Wv;
    const float* bm = (z == 0) ? bq : (z == 1) ? bk : bv;
    float* dst = (z == 0) ? g_q : (z == 1) ? g_k : g_v;

    const int bn0 = blockIdx.x * QKV_BN;   // output cols (== head * 64)
    const int bm0 = blockIdx.y * QKV_BM;   // output rows

    __shared__ __align__(32) float sm[QKV_BM * CS_STRIDE];  // 9216 floats, 36.9KB
    float* As = sm;                               // [128][40]
    float* Bs = sm + QKV_BM * AS_STRIDE;          // [32][72]
    float* Cs = sm;                               // [128][72] (reused)

    const int tid = threadIdx.x;
    const int w  = tid >> 5;
    const int wm = w >> 1;     // 0..3
    const int wn = w & 1;      // 0..1

    // A load map: 2 threads per row, 16 floats each
    const int ar = tid >> 1;          // 0..127
    const int aseg = (tid & 1) * 16;
    // B load map: 8 threads per row, 8 floats each
    const int br = tid >> 3;          // 0..31
    const int bseg = (tid & 7) * 8;

    wmma::fragment<wmma::accumulator, 16, 16, 8, float> cf[2][2];
    #pragma unroll
    for (int i = 0; i < 2; i++)
        #pragma unroll
        for (int j = 0; j < 2; j++)
            wmma::fill_fragment(cf[i][j], 0.0f);

    for (int kk = 0; kk < EMB; kk += QKV_BK) {
        __syncthreads();
        // Load A: rows bm0+ar, cols kk+aseg..+15
        #pragma unroll
        for (int q = 0; q < 4; q++) {
            float4 v = *(const float4*)&hs[(size_t)(bm0 + ar) * EMB + kk + aseg + q * 4];
            *(float4*)&As[ar * AS_STRIDE + aseg + q * 4] = v;
        }
        // Load B: rows kk+br, cols bn0+bseg..+7
        #pragma unroll
        for (int q = 0; q < 2; q++) {
            float4 v = *(const float4*)&Wm[(size_t)(kk + br) * EMB + bn0 + bseg + q * 4];
            *(float4*)&Bs[br * BS_STRIDE + bseg + q * 4] = v;
        }
        __syncthreads();

        #pragma unroll
        for (int ks = 0; ks < 4; ks++) {
            wmma::fragment<wmma::matrix_a, 16, 16, 8, wmma::precision::tf32, wmma::row_major> af[2];
            wmma::fragment<wmma::matrix_b, 16, 16, 8, wmma::precision::tf32, wmma::row_major> bf[2];
            #pragma unroll
            for (int m = 0; m < 2; m++) {
                wmma::load_matrix_sync(af[m], &As[(wm * 32 + m * 16) * AS_STRIDE + ks * 8], AS_STRIDE);
                #pragma unroll
                for (int e = 0; e < af[m].num_elements; e++)
                    af[m].x[e] = wmma::__float_to_tf32(af[m].x[e]);
            }
            #pragma unroll
            for (int n = 0; n < 2; n++) {
                wmma::load_matrix_sync(bf[n], &Bs[(ks * 8) * BS_STRIDE + wn * 32 + n * 16], BS_STRIDE);
                #pragma unroll
                for (int e = 0; e < bf[n].num_elements; e++)
                    bf[n].x[e] = wmma::__float_to_tf32(bf[n].x[e]);
            }
            #pragma unroll
            for (int m = 0; m < 2; m++)
                #pragma unroll
                for (int n = 0; n < 2; n++)
                    wmma::mma_sync(cf[m][n], af[m], bf[n], cf[m][n]);
        }
    }

    // Epilogue: frags -> smem -> bias+scale -> head-major global
    __syncthreads();
    #pragma unroll
    for (int m = 0; m < 2; m++)
        #pragma unroll
        for (int n = 0; n < 2; n++)
            wmma::store_matrix_sync(&Cs[(wm * 32 + m * 16) * CS_STRIDE + wn * 32 + n * 16],
                                    cf[m][n], CS_STRIDE, wmma::mem_row_major);
    __syncthreads();

    const int h = bn0 >> 6;
    const float scl = (z == 0) ? 0.125f : 1.0f;
    #pragma unroll
    for (int it = 0; it < 32; it++) {
        int e = it * 256 + tid;
        int r = e >> 6;
        int c = e & 63;
        float v = (Cs[r * CS_STRIDE + c] + bm[bn0 + c]) * scl;
        dst[((size_t)h * SQ + bm0 + r) * HD + c] = v;
    }
}

// ---------------------------------------------------------------------------
// Banded attention, flash-style online softmax. fp32.
// grid = (SQ/128, NH), block = 128. 128 queries x 64-key steps, 8x8 micro-tiles.
// 10 aligned 64-key tiles cover the band for 128 queries.
// ---------------------------------------------------------------------------
#define QT 128
#define QSTRIDE (QT + 4)    // 132
#define KPAD 68
#define ATT_SMEM_FLOATS (2 * 64 * QSTRIDE + 2 * 64 * KPAD + 64)

__global__ __launch_bounds__(128, 2) void attn_kernel(
    const float* __restrict__ amask,
    const unsigned char* __restrict__ qmask,
    float* __restrict__ out)
{
    extern __shared__ float smem[];
    float (*QsT)[QSTRIDE] = (float(*)[QSTRIDE])(smem);                       // [64][132]
    float (*KsT)[KPAD]    = (float(*)[KPAD])(smem + 64 * QSTRIDE);           // [64][68]
    float (*Vs)[KPAD]     = (float(*)[KPAD])(smem + 64 * QSTRIDE + 64 * KPAD);
    float (*Pt)[QSTRIDE]  = (float(*)[QSTRIDE])(smem + 64 * QSTRIDE + 2 * 64 * KPAD);
    float* kmsk = smem + 2 * 64 * QSTRIDE + 2 * 64 * KPAD;

    const int h  = blockIdx.y;
    const int q0 = blockIdx.x * QT;

    const int tid = threadIdx.x;
    const int ty = tid >> 3, tx = tid & 7;
    const int i0 = ty * 8;        // 8 query rows owned by this thread
    const int c0 = tx * 8;        // 8 key cols (score) / head dims (PV)

    // Load Q tile transposed: QsT[d][i]  (one row per thread)
    {
        const float* qptr = &g_q[((size_t)h * SQ + q0 + tid) * HD];
        #pragma unroll
        for (int c = 0; c < 16; c++) {
            float4 v = *(const float4*)&qptr[c * 4];
            QsT[c * 4 + 0][tid] = v.x;
            QsT[c * 4 + 1][tid] = v.y;
            QsT[c * 4 + 2][tid] = v.z;
            QsT[c * 4 + 3][tid] = v.w;
        }
    }

    float m_i[8], l_i[8], O[8][8];
    #pragma unroll
    for (int ii = 0; ii < 8; ii++) {
        m_i[ii] = -1e30f;
        l_i[ii] = 0.0f;
        #pragma unroll
        for (int cc = 0; cc < 8; cc++) O[ii][cc] = 0.0f;
    }

    const int li2 = tid >> 1;            // 0..63 (K/V row)
    const int hcol = (tid & 1) * 32;     // half-row of 32 floats

    for (int t = 0; t < 10; t++) {
        const int jb = q0 - 256 + t * 64;      // aligned tile: fully in or out
        if (jb < 0 || jb >= SQ) continue;

        __syncthreads();   // previous iteration's reads of KsT/Vs/Pt done

        // Load K tile transposed, V tile natural, key mask
        {
            const float* kptr = &g_k[((size_t)h * SQ + jb + li2) * HD + hcol];
            const float* vptr = &g_v[((size_t)h * SQ + jb + li2) * HD + hcol];
            #pragma unroll
            for (int c = 0; c < 8; c++) {
                float4 kv = *(const float4*)&kptr[c * 4];
                KsT[hcol + c * 4 + 0][li2] = kv.x;
                KsT[hcol + c * 4 + 1][li2] = kv.y;
                KsT[hcol + c * 4 + 2][li2] = kv.z;
                KsT[hcol + c * 4 + 3][li2] = kv.w;
                float4 vv = *(const float4*)&vptr[c * 4];
                *(float4*)&Vs[li2][hcol + c * 4] = vv;
            }
            if (tid < 64)
                kmsk[tid] = (amask[jb + tid] != 0.0f) ? -1e8f : 0.0f;
        }
        __syncthreads();

        // Scores: s[i][j] = sum_d QsT[d][i] * KsT[d][j]
        float s[8][8] = {};
        #pragma unroll 8
        for (int d = 0; d < 64; d++) {
            float a[8], b[8];
            *(float4*)&a[0] = *(const float4*)&QsT[d][i0];
            *(float4*)&a[4] = *(const float4*)&QsT[d][i0 + 4];
            *(float4*)&b[0] = *(const float4*)&KsT[d][c0];
            *(float4*)&b[4] = *(const float4*)&KsT[d][c0 + 4];
            #pragma unroll
            for (int ii = 0; ii < 8; ii++)
                #pragma unroll
                for (int jj = 0; jj < 8; jj++)
                    s[ii][jj] = fmaf(a[ii], b[jj], s[ii][jj]);
        }

        // Band mask + key mask + online softmax (per-row over 8-lane tx group)
        #pragma unroll
        for (int ii = 0; ii < 8; ii++) {
            const int gi = q0 + i0 + ii;
            float rowm = -1e30f;
            #pragma unroll
            for (int jj = 0; jj < 8; jj++) {
                const int gj = jb + c0 + jj;
                const int diff = gi - gj;
                const bool valid = (diff <= WIN) && (diff >= -WIN);
                float sv = valid ? (s[ii][jj] + kmsk[c0 + jj]) : -1e30f;
                s[ii][jj] = sv;
                rowm = fmaxf(rowm, sv);
            }
            #pragma unroll
            for (int o = 4; o >= 1; o >>= 1)
                rowm = fmaxf(rowm, __shfl_xor_sync(0xffffffffu, rowm, o, 8));

            const float newm = fmaxf(m_i[ii], rowm);
            const float rescale = __expf(m_i[ii] - newm);
            m_i[ii] = newm;

            float rs = 0.0f;
            #pragma unroll
            for (int jj = 0; jj < 8; jj++) {
                float p = __expf(s[ii][jj] - newm);
                s[ii][jj] = p;
                rs += p;
            }
            #pragma unroll
            for (int o = 4; o >= 1; o >>= 1)
                rs += __shfl_xor_sync(0xffffffffu, rs, o, 8);

            l_i[ii] = l_i[ii] * rescale + rs;
            #pragma unroll
            for (int cc = 0; cc < 8; cc++) O[ii][cc] *= rescale;
        }

        // Write P transposed: Pt[j][i]
        #pragma unroll
        for (int jj = 0; jj < 8; jj++)
            #pragma unroll
            for (int ii = 0; ii < 8; ii++)
                Pt[c0 + jj][i0 + ii] = s[ii][jj];
        __syncthreads();

        // O[i][dd] += sum_j Pt[j][i] * Vs[j][dd]
        #pragma unroll 8
        for (int j = 0; j < 64; j++) {
            float a[8], b[8];
            *(float4*)&a[0] = *(const float4*)&Pt[j][i0];
            *(float4*)&a[4] = *(const float4*)&Pt[j][i0 + 4];
            *(float4*)&b[0] = *(const float4*)&Vs[j][c0];
            *(float4*)&b[4] = *(const float4*)&Vs[j][c0 + 4];
            #pragma unroll
            for (int ii = 0; ii < 8; ii++)
                #pragma unroll
                for (int cc = 0; cc < 8; cc++)
                    O[ii][cc] = fmaf(a[ii], b[cc], O[ii][cc]);
        }
    }

    // Epilogue: normalize, apply is_index_masked, write (S, E) output
    #pragma unroll
    for (int ii = 0; ii < 8; ii++) {
        const int gi = q0 + i0 + ii;
        const float inv = 1.0f / l_i[ii];
        const bool zm = (qmask[gi] != 0);
        float4 o1, o2;
        o1.x = zm ? 0.0f : O[ii][0] * inv;
        o1.y = zm ? 0.0f : O[ii][1] * inv;
        o1.z = zm ? 0.0f : O[ii][2] * inv;
        o1.w = zm ? 0.0f : O[ii][3] * inv;
        o2.x = zm ? 0.0f : O[ii][4] * inv;
        o2.y = zm ? 0.0f : O[ii][5] * inv;
        o2.z = zm ? 0.0f : O[ii][6] * inv;
        o2.w = zm ? 0.0f : O[ii][7] * inv;
        float* op = &out[(size_t)gi * EMB + h * HD + c0];
        *(float4*)&op[0] = o1;
        *(float4*)&op[4] = o2;
    }
}

// ---------------------------------------------------------------------------
// Launch
// ---------------------------------------------------------------------------
extern "C" void kernel_launch(void* const* d_in, const int* in_sizes, int n_in,
                              void* d_out, int out_size)
{
    const float* hs            = (const float*)d_in[0];
    const float* amask         = (const float*)d_in[1];
    const unsigned char* qmask = (const unsigned char*)d_in[2];
    const float* Wq = (const float*)d_in[3];
    const float* bq = (const float*)d_in[4];
    const float* Wk = (const float*)d_in[5];
    const float* bk = (const float*)d_in[6];
    const float* Wv = (const float*)d_in[7];
    const float* bv = (const float*)d_in[8];
    float* out = (float*)d_out;

    qkv_kernel<<<dim3(EMB / QKV_BN, SQ / QKV_BM, 3), 256>>>(hs, Wq, bq, Wk, bk, Wv, bv);

    const int smem_bytes = ATT_SMEM_FLOATS * (int)sizeof(float);
    cudaFuncSetAttribute(attn_kernel,
                         cudaFuncAttributeMaxDynamicSharedMemorySize, smem_bytes);
    attn_kernel<<<dim3(SQ / QT, NH), 128, smem_bytes>>>(amask, qmask, out);
}

// round 6
// speedup vs baseline: 3.2297x; 3.2297x over previous
#include <cuda_runtime.h>
#include <cuda_bf16.h>
#include <math.h>
#include <stdint.h>

// Problem constants
#define SQ   4096
#define EMB  768
#define NH   12
#define HD   64
#define WIN  256
#define K2   2304   // 3 * 768 split-GEMM depth

// Scratch (allocation-free rule: __device__ globals)
__device__ float g_q[NH * SQ * HD];
__device__ float g_k[NH * SQ * HD];
__device__ float g_v[NH * SQ * HD];
__device__ __align__(16) __nv_bfloat16 g_as[(size_t)SQ * K2];        // A' [4096][2304] slabs [hi,hi,lo]
__device__ __align__(16) __nv_bfloat16 g_bs[(size_t)3 * EMB * K2];   // B'_z [768 n][2304 k] slabs [hi,lo,hi]

// ---------------------------------------------------------------------------
// PTX helpers — tcgen05 ones are only referenced under the sm_103a guard.
// ---------------------------------------------------------------------------
__device__ __forceinline__ uint32_t smem_u32(const void* p) {
    uint32_t a;
    asm("{ .reg .u64 t; cvta.to.shared.u64 t, %1; cvt.u32.u64 %0, t; }" : "=r"(a) : "l"(p));
    return a;
}
__device__ __forceinline__ uint32_t elect_one() {
    uint32_t pred;
    asm volatile("{\n\t.reg .pred p;\n\telect.sync _|p, 0xFFFFFFFF;\n\tselp.b32 %0, 1, 0, p;\n\t}" : "=r"(pred));
    return pred;
}
__device__ __forceinline__ void mbar_init(uint32_t mb, uint32_t cnt) {
    asm volatile("mbarrier.init.shared.b64 [%0], %1;" :: "r"(mb), "r"(cnt) : "memory");
}
__device__ __forceinline__ void mbar_wait(uint32_t mb, uint32_t phase) {
    asm volatile(
        "{\n\t.reg .pred P1;\n\t"
        "WL_%=:\n\t"
        "mbarrier.try_wait.parity.acquire.cta.shared::cta.b64 P1, [%0], %1, 0x989680;\n\t"
        "@P1 bra.uni WD_%=;\n\t"
        "bra.uni WL_%=;\n\t"
        "WD_%=:\n\t}"
        :: "r"(mb), "r"(phase) : "memory");
}

#if defined(__CUDA_ARCH_FEAT_SM103_ALL)
#define TC_OK 1
#else
#define TC_OK 0
#endif

#if TC_OK
__device__ __forceinline__ void mma_f16_ss(uint32_t d, uint64_t a, uint64_t b,
                                           uint32_t idesc, bool acc) {
    uint32_t en = acc ? 1u : 0u;
    asm volatile(
        "{\n\t.reg .pred p;\n\tsetp.ne.u32 p, %5, 0;\n\t"
        "tcgen05.mma.cta_group::1.kind::f16 [%0], %1, %2, %3, {%4, %4, %4, %4}, p;\n\t}"
        :: "r"(d), "l"(a), "l"(b), "r"(idesc), "r"(0u), "r"(en) : "memory");
}
__device__ __forceinline__ void tc_commit(uint32_t mb) {
    asm volatile("tcgen05.commit.cta_group::1.mbarrier::arrive::one.shared::cluster.b64 [%0];"
                 :: "r"(mb) : "memory");
}
#define TC_LD_X32(r, addr) \
    asm volatile( \
        "tcgen05.ld.sync.aligned.32x32b.x32.b32 " \
        "{%0, %1, %2, %3, %4, %5, %6, %7, " \
        " %8, %9, %10, %11, %12, %13, %14, %15, " \
        " %16, %17, %18, %19, %20, %21, %22, %23, " \
        " %24, %25, %26, %27, %28, %29, %30, %31}, [%32];" \
        : "=r"((r)[0]),  "=r"((r)[1]),  "=r"((r)[2]),  "=r"((r)[3]), \
          "=r"((r)[4]),  "=r"((r)[5]),  "=r"((r)[6]),  "=r"((r)[7]), \
          "=r"((r)[8]),  "=r"((r)[9]),  "=r"((r)[10]), "=r"((r)[11]), \
          "=r"((r)[12]), "=r"((r)[13]), "=r"((r)[14]), "=r"((r)[15]), \
          "=r"((r)[16]), "=r"((r)[17]), "=r"((r)[18]), "=r"((r)[19]), \
          "=r"((r)[20]), "=r"((r)[21]), "=r"((r)[22]), "=r"((r)[23]), \
          "=r"((r)[24]), "=r"((r)[25]), "=r"((r)[26]), "=r"((r)[27]), \
          "=r"((r)[28]), "=r"((r)[29]), "=r"((r)[30]), "=r"((r)[31]) \
        : "r"(addr))
#endif

static __device__ __forceinline__ uint64_t make_desc(uint32_t addr) {
    const uint64_t base = (2ull << 61) | (1ull << 46) | (64ull << 32) | (1ull << 16);
    return base | ((uint64_t)(addr >> 4) & 0x3FFF);
}

// ---------------------------------------------------------------------------
// Split pre-pass: hs -> g_as (slabs hi,hi,lo)
// ---------------------------------------------------------------------------
__global__ void split_hs_kernel(const float* __restrict__ hs)
{
    int i = blockIdx.x * 256 + threadIdx.x;     // over 4096*768
    float x = hs[i];
    __nv_bfloat16 h = __float2bfloat16(x);
    __nv_bfloat16 l = __float2bfloat16(x - __bfloat162float(h));
    int row = i / EMB, k = i - row * EMB;
    __nv_bfloat16* p = &g_as[(size_t)row * K2];
    p[k] = h; p[EMB + k] = h; p[2 * EMB + k] = l;
}

// Split + transpose weights: W_z[k][n] -> g_bs[z][n][slabs hi,lo,hi of k]
__global__ void split_w_kernel(const float* __restrict__ Wq,
                               const float* __restrict__ Wk,
                               const float* __restrict__ Wv)
{
    __shared__ float t[32][33];
    const int z = blockIdx.z;
    const float* W = (z == 0) ? Wq : (z == 1) ? Wk : Wv;
    int k = blockIdx.y * 32 + threadIdx.y;
    int n = blockIdx.x * 32 + threadIdx.x;
    t[threadIdx.y][threadIdx.x] = W[(size_t)k * EMB + n];
    __syncthreads();
    int nn = blockIdx.x * 32 + threadIdx.y;
    int kk = blockIdx.y * 32 + threadIdx.x;
    float x = t[threadIdx.x][threadIdx.y];
    __nv_bfloat16 h = __float2bfloat16(x);
    __nv_bfloat16 l = __float2bfloat16(x - __bfloat162float(h));
    __nv_bfloat16* p = &g_bs[((size_t)z * EMB + nn) * K2];
    p[kk] = h; p[EMB + kk] = l; p[2 * EMB + kk] = h;
}

// ---------------------------------------------------------------------------
// QKV GEMM on tcgen05: C(4096x768 per z) = A'(4096x2304) . B'_z(768x2304)^T
// Per CTA: 128 rows x 256 cols (4 heads). 36 K-chunks of 64, 2-stage pipeline.
// grid = (768/256, 4096/128, 3) = (3, 32, 3), block = 256.
// Guarded: tcgen05 body only for the sm_103a cubin; generic FFMA fallback for
// the compute_103 PTX pass (correct if ever JIT'd, never used on GB300).
// ---------------------------------------------------------------------------
#define STAGE_BYTES 49152                 // A 16KB + B 32KB
#define QKV_SMEM (2 * STAGE_BYTES + 32)   // + ctrl/mbars
#define QKV_IDESC 0x8400490u              // f32 acc, bf16 a/b, N=256, M=128

__global__ __launch_bounds__(256) void qkv_mma_kernel(
    const float* __restrict__ bq, const float* __restrict__ bk,
    const float* __restrict__ bv)
{
    const int z = blockIdx.z;
    const float* bias = (z == 0) ? bq : (z == 1) ? bk : bv;
    float* dst = (z == 0) ? g_q : (z == 1) ? g_k : g_v;
    const int n0 = blockIdx.x * 256;
    const int m0 = blockIdx.y * 128;
    const int tid = threadIdx.x;

#if TC_OK
    extern __shared__ __align__(1024) char sm[];
    const uint32_t sb = smem_u32(sm);
    const int wid = tid >> 5, lid = tid & 31;

    const uint32_t ctrl = sb + 2 * STAGE_BYTES;       // tmem ptr (4B)
    const uint32_t mb[2] = { sb + 2 * STAGE_BYTES + 8, sb + 2 * STAGE_BYTES + 16 };

    if (tid == 0) { mbar_init(mb[0], 1); mbar_init(mb[1], 1); }
    if (wid == 0) {
        asm volatile("tcgen05.alloc.cta_group::1.sync.aligned.shared::cta.b32 [%0], %1;"
                     :: "r"(ctrl), "r"(256u) : "memory");
        asm volatile("tcgen05.relinquish_alloc_permit.cta_group::1.sync.aligned;");
    }
    __syncthreads();
    uint32_t tmem;
    asm volatile("ld.shared.b32 %0, [%1];" : "=r"(tmem) : "r"(ctrl));

    const __nv_bfloat16* Arow = &g_as[(size_t)m0 * K2];
    const __nv_bfloat16* Brow = &g_bs[((size_t)z * EMB + n0) * K2];

    int ph[2] = { 0, 0 };

    for (int c = 0; c < 36; c++) {
        const int s = c & 1;
        if (c >= 2) { mbar_wait(mb[s], ph[s]); ph[s] ^= 1; }
        const int kk = c * 64;
        char* stA = sm + s * STAGE_BYTES;
        char* stB = stA + 16384;

        // A chunk: 128 rows x 64 bf16 (128B rows), SW128-swizzled 16B stores
        #pragma unroll
        for (int j = 0; j < 4; j++) {
            int cid = tid + j * 256;
            int r = cid >> 3, c16 = cid & 7;
            uint32_t off = (uint32_t)(r * 128 + c16 * 16);
            off ^= (off >> 3) & 0x70;
            *(uint4*)(stA + off) = *(const uint4*)(Arow + (size_t)r * K2 + kk + c16 * 8);
        }
        // B chunk: 256 rows x 64 bf16
        #pragma unroll
        for (int j = 0; j < 8; j++) {
            int cid = tid + j * 256;
            int r = cid >> 3, c16 = cid & 7;
            uint32_t off = (uint32_t)(r * 128 + c16 * 16);
            off ^= (off >> 3) & 0x70;
            *(uint4*)(stB + off) = *(const uint4*)(Brow + (size_t)r * K2 + kk + c16 * 8);
        }
        asm volatile("fence.proxy.async.shared::cta;" ::: "memory");
        __syncthreads();

        if (wid == 0) {
            if (elect_one()) {
                uint64_t da = make_desc(sb + s * STAGE_BYTES);
                uint64_t db = make_desc(sb + s * STAGE_BYTES + 16384);
                #pragma unroll
                for (int k = 0; k < 4; k++)
                    mma_f16_ss(tmem, da + k * 2, db + k * 2, QKV_IDESC, (c > 0) || (k > 0));
                tc_commit(mb[s]);
            }
        }
    }

    // Final: chunk 35 committed on mb[1]
    mbar_wait(mb[1], ph[1]);
    asm volatile("tcgen05.fence::after_thread_sync;" ::: "memory");

    // Epilogue: warpgroup 0 reads D (128 lanes x 256 cols), bias+scale, scatter
    if (wid < 4) {
        const int r = wid * 32 + lid;
        const float scl = (z == 0) ? 0.125f : 1.0f;
        #pragma unroll
        for (int cb = 0; cb < 8; cb++) {
            uint32_t dr[32];
            TC_LD_X32(dr, tmem + cb * 32);
            asm volatile("tcgen05.wait::ld.sync.aligned;" ::: "memory");
            const int nbase = n0 + cb * 32;
            const int head = nbase >> 6;
            float* op = &dst[((size_t)head * SQ + m0 + r) * HD + (nbase & 63)];
            #pragma unroll
            for (int q = 0; q < 32; q += 4) {
                float4 v;
                v.x = (__uint_as_float(dr[q + 0]) + bias[nbase + q + 0]) * scl;
                v.y = (__uint_as_float(dr[q + 1]) + bias[nbase + q + 1]) * scl;
                v.z = (__uint_as_float(dr[q + 2]) + bias[nbase + q + 2]) * scl;
                v.w = (__uint_as_float(dr[q + 3]) + bias[nbase + q + 3]) * scl;
                *(float4*)&op[q] = v;
            }
        }
    }
    __syncthreads();
    if (wid == 0) {
        asm volatile("tcgen05.dealloc.cta_group::1.sync.aligned.b32 %0, %1;"
                     :: "r"(tmem), "r"(256u));
    }
#else
    // Generic fallback (compute_103 PTX pass only; never runs on GB300 —
    // the sm_103a cubin takes precedence). Correct naive split-GEMM.
    const int r = tid >> 1;                 // 0..127
    const int cb0 = (tid & 1) * 128;        // half of the 256 cols
    const float scl = (z == 0) ? 0.125f : 1.0f;
    const __nv_bfloat16* a = &g_as[(size_t)(m0 + r) * K2];
    for (int cc = 0; cc < 128; cc++) {
        const int n = n0 + cb0 + cc;
        const __nv_bfloat16* b = &g_bs[((size_t)z * EMB + n) * K2];
        float acc = 0.0f;
        for (int k = 0; k < K2; k++)
            acc += __bfloat162float(a[k]) * __bfloat162float(b[k]);
        const int head = n >> 6;
        dst[((size_t)head * SQ + m0 + r) * HD + (n & 63)] = (acc + bias[n]) * scl;
    }
#endif
}

// ---------------------------------------------------------------------------
// Banded attention, flash-style online softmax (R1 proven version).
// grid = (SQ/64, NH), block = 256.
// ---------------------------------------------------------------------------
#define TPAD 68
#define ATT_SMEM_FLOATS (4 * 64 * TPAD + 64)

__global__ __launch_bounds__(256, 2) void attn_kernel(
    const float* __restrict__ amask,
    const unsigned char* __restrict__ qmask,
    float* __restrict__ out)
{
    extern __shared__ float smem[];
    float (*QsT)[TPAD] = (float(*)[TPAD])(smem);
    float (*KsT)[TPAD] = (float(*)[TPAD])(smem + 64 * TPAD);
    float (*Vs)[TPAD]  = (float(*)[TPAD])(smem + 2 * 64 * TPAD);
    float (*Pt)[TPAD]  = (float(*)[TPAD])(smem + 3 * 64 * TPAD);
    float* kmsk = smem + 4 * 64 * TPAD;

    const int h  = blockIdx.y;
    const int q0 = blockIdx.x * 64;

    const int tid = threadIdx.x;
    const int ty = tid >> 4, tx = tid & 15;
    const int i0 = ty * 4;
    const int c0 = tx * 4;

    const int li = tid >> 2;
    const int lq = tid & 3;

    {
        const float* qptr = &g_q[((size_t)h * SQ + q0 + li) * HD];
        #pragma unroll
        for (int c = 0; c < 4; c++) {
            float4 v = *(const float4*)&qptr[lq * 16 + c * 4];
            QsT[lq * 16 + c * 4 + 0][li] = v.x;
            QsT[lq * 16 + c * 4 + 1][li] = v.y;
            QsT[lq * 16 + c * 4 + 2][li] = v.z;
            QsT[lq * 16 + c * 4 + 3][li] = v.w;
        }
    }

    float m_i[4], l_i[4], O[4][4];
    #pragma unroll
    for (int ii = 0; ii < 4; ii++) {
        m_i[ii] = -1e30f;
        l_i[ii] = 0.0f;
        #pragma unroll
        for (int cc = 0; cc < 4; cc++) O[ii][cc] = 0.0f;
    }

    for (int t = 0; t < 9; t++) {
        const int jb = q0 - 256 + t * 64;
        if (jb < 0 || jb >= SQ) continue;

        __syncthreads();

        {
            const float* kptr = &g_k[((size_t)h * SQ + jb + li) * HD];
            const float* vptr = &g_v[((size_t)h * SQ + jb + li) * HD];
            #pragma unroll
            for (int c = 0; c < 4; c++) {
                float4 kv = *(const float4*)&kptr[lq * 16 + c * 4];
                KsT[lq * 16 + c * 4 + 0][li] = kv.x;
                KsT[lq * 16 + c * 4 + 1][li] = kv.y;
                KsT[lq * 16 + c * 4 + 2][li] = kv.z;
                KsT[lq * 16 + c * 4 + 3][li] = kv.w;
                float4 vv = *(const float4*)&vptr[lq * 16 + c * 4];
                *(float4*)&Vs[li][lq * 16 + c * 4] = vv;
            }
            if (tid < 64)
                kmsk[tid] = (amask[jb + tid] != 0.0f) ? -1e8f : 0.0f;
        }
        __syncthreads();

        float s[4][4] = {};
        #pragma unroll 16
        for (int d = 0; d < 64; d++) {
            float4 av = *(const float4*)&QsT[d][i0];
            float4 bv = *(const float4*)&KsT[d][c0];
            float a[4] = {av.x, av.y, av.z, av.w};
            float b[4] = {bv.x, bv.y, bv.z, bv.w};
            #pragma unroll
            for (int ii = 0; ii < 4; ii++)
                #pragma unroll
                for (int jj = 0; jj < 4; jj++)
                    s[ii][jj] = fmaf(a[ii], b[jj], s[ii][jj]);
        }

        #pragma unroll
        for (int ii = 0; ii < 4; ii++) {
            const int gi = q0 + i0 + ii;
            float rowm = -1e30f;
            #pragma unroll
            for (int jj = 0; jj < 4; jj++) {
                const int gj = jb + c0 + jj;
                const int diff = gi - gj;
                const bool valid = (diff <= WIN) && (diff >= -WIN);
                float sv = valid ? (s[ii][jj] + kmsk[c0 + jj]) : -1e30f;
                s[ii][jj] = sv;
                rowm = fmaxf(rowm, sv);
            }
            #pragma unroll
            for (int o = 8; o >= 1; o >>= 1)
                rowm = fmaxf(rowm, __shfl_xor_sync(0xffffffffu, rowm, o, 16));

            const float newm = fmaxf(m_i[ii], rowm);
            const float rescale = __expf(m_i[ii] - newm);
            m_i[ii] = newm;

            float rs = 0.0f;
            #pragma unroll
            for (int jj = 0; jj < 4; jj++) {
                float p = __expf(s[ii][jj] - newm);
                s[ii][jj] = p;
                rs += p;
            }
            #pragma unroll
            for (int o = 8; o >= 1; o >>= 1)
                rs += __shfl_xor_sync(0xffffffffu, rs, o, 16);

            l_i[ii] = l_i[ii] * rescale + rs;
            #pragma unroll
            for (int cc = 0; cc < 4; cc++) O[ii][cc] *= rescale;
        }

        #pragma unroll
        for (int jj = 0; jj < 4; jj++)
            #pragma unroll
            for (int ii = 0; ii < 4; ii++)
                Pt[c0 + jj][i0 + ii] = s[ii][jj];
        __syncthreads();

        #pragma unroll 16
        for (int j = 0; j < 64; j++) {
            float4 av = *(const float4*)&Pt[j][i0];
            float4 bv = *(const float4*)&Vs[j][c0];
            float a[4] = {av.x, av.y, av.z, av.w};
            float b[4] = {bv.x, bv.y, bv.z, bv.w};
            #pragma unroll
            for (int ii = 0; ii < 4; ii++)
                #pragma unroll
                for (int cc = 0; cc < 4; cc++)
                    O[ii][cc] = fmaf(a[ii], b[cc], O[ii][cc]);
        }
    }

    #pragma unroll
    for (int ii = 0; ii < 4; ii++) {
        const int gi = q0 + i0 + ii;
        const float inv = 1.0f / l_i[ii];
        const bool zm = (qmask[gi] != 0);
        #pragma unroll
        for (int cc = 0; cc < 4; cc++) {
            float v = zm ? 0.0f : O[ii][cc] * inv;
            out[(size_t)gi * EMB + h * HD + c0 + cc] = v;
        }
    }
}

// ---------------------------------------------------------------------------
// Launch
// ---------------------------------------------------------------------------
extern "C" void kernel_launch(void* const* d_in, const int* in_sizes, int n_in,
                              void* d_out, int out_size)
{
    const float* hs            = (const float*)d_in[0];
    const float* amask         = (const float*)d_in[1];
    const unsigned char* qmask = (const unsigned char*)d_in[2];
    const float* Wq = (const float*)d_in[3];
    const float* bq = (const float*)d_in[4];
    const float* Wk = (const float*)d_in[5];
    const float* bk = (const float*)d_in[6];
    const float* Wv = (const float*)d_in[7];
    const float* bv = (const float*)d_in[8];
    float* out = (float*)d_out;

    // 1) bf16 hi/lo split pre-pass
    split_hs_kernel<<<(SQ * EMB) / 256, 256>>>(hs);
    split_w_kernel<<<dim3(EMB / 32, EMB / 32, 3), dim3(32, 32)>>>(Wq, Wk, Wv);

    // 2) tcgen05 bf16-split QKV GEMM
    cudaFuncSetAttribute(qkv_mma_kernel,
                         cudaFuncAttributeMaxDynamicSharedMemorySize, QKV_SMEM);
    qkv_mma_kernel<<<dim3(EMB / 256, SQ / 128, 3), 256, QKV_SMEM>>>(bq, bk, bv);

    // 3) banded attention (fp32, proven)
    const int att_smem = ATT_SMEM_FLOATS * (int)sizeof(float);
    cudaFuncSetAttribute(attn_kernel,
                         cudaFuncAttributeMaxDynamicSharedMemorySize, att_smem);
    attn_kernel<<<dim3(SQ / 64, NH), 256, att_smem>>>(amask, qmask, out);
}

// round 7
// speedup vs baseline: 4.1016x; 1.2700x over previous
#include <cuda_runtime.h>
#include <cuda_bf16.h>
#include <math.h>
#include <stdint.h>

// Problem constants
#define SQ   4096
#define EMB  768
#define NH   12
#define HD   64
#define WIN  256
#define K2   2304   // 3 * 768 split-GEMM depth

// Scratch (allocation-free rule: __device__ globals)
__device__ float g_q[NH * SQ * HD];
__device__ float g_k[NH * SQ * HD];
__device__ float g_v[NH * SQ * HD];
__device__ __align__(16) __nv_bfloat16 g_as[(size_t)SQ * K2];        // A' [4096][2304] slabs [hi,hi,lo]
__device__ __align__(16) __nv_bfloat16 g_bs[(size_t)3 * EMB * K2];   // B'_z [768 n][2304 k] slabs [hi,lo,hi]

// ---------------------------------------------------------------------------
// PTX helpers — tcgen05 only under the sm_103a feature guard.
// ---------------------------------------------------------------------------
__device__ __forceinline__ uint32_t smem_u32(const void* p) {
    uint32_t a;
    asm("{ .reg .u64 t; cvta.to.shared.u64 t, %1; cvt.u32.u64 %0, t; }" : "=r"(a) : "l"(p));
    return a;
}
__device__ __forceinline__ uint32_t elect_one() {
    uint32_t pred;
    asm volatile("{\n\t.reg .pred p;\n\telect.sync _|p, 0xFFFFFFFF;\n\tselp.b32 %0, 1, 0, p;\n\t}" : "=r"(pred));
    return pred;
}
__device__ __forceinline__ void mbar_init(uint32_t mb, uint32_t cnt) {
    asm volatile("mbarrier.init.shared.b64 [%0], %1;" :: "r"(mb), "r"(cnt) : "memory");
}
__device__ __forceinline__ void mbar_wait(uint32_t mb, uint32_t phase) {
    asm volatile(
        "{\n\t.reg .pred P1;\n\t"
        "WL_%=:\n\t"
        "mbarrier.try_wait.parity.acquire.cta.shared::cta.b64 P1, [%0], %1, 0x989680;\n\t"
        "@P1 bra.uni WD_%=;\n\t"
        "bra.uni WL_%=;\n\t"
        "WD_%=:\n\t}"
        :: "r"(mb), "r"(phase) : "memory");
}

#if defined(__CUDA_ARCH_FEAT_SM103_ALL)
#define TC_OK 1
#else
#define TC_OK 0
#endif

#if TC_OK
__device__ __forceinline__ void mma_f16_ss(uint32_t d, uint64_t a, uint64_t b,
                                           uint32_t idesc, bool acc) {
    uint32_t en = acc ? 1u : 0u;
    asm volatile(
        "{\n\t.reg .pred p;\n\tsetp.ne.u32 p, %5, 0;\n\t"
        "tcgen05.mma.cta_group::1.kind::f16 [%0], %1, %2, %3, {%4, %4, %4, %4}, p;\n\t}"
        :: "r"(d), "l"(a), "l"(b), "r"(idesc), "r"(0u), "r"(en) : "memory");
}
__device__ __forceinline__ void tc_commit(uint32_t mb) {
    asm volatile("tcgen05.commit.cta_group::1.mbarrier::arrive::one.shared::cluster.b64 [%0];"
                 :: "r"(mb) : "memory");
}
#define TC_LD_X32(r, addr) \
    asm volatile( \
        "tcgen05.ld.sync.aligned.32x32b.x32.b32 " \
        "{%0, %1, %2, %3, %4, %5, %6, %7, " \
        " %8, %9, %10, %11, %12, %13, %14, %15, " \
        " %16, %17, %18, %19, %20, %21, %22, %23, " \
        " %24, %25, %26, %27, %28, %29, %30, %31}, [%32];" \
        : "=r"((r)[0]),  "=r"((r)[1]),  "=r"((r)[2]),  "=r"((r)[3]), \
          "=r"((r)[4]),  "=r"((r)[5]),  "=r"((r)[6]),  "=r"((r)[7]), \
          "=r"((r)[8]),  "=r"((r)[9]),  "=r"((r)[10]), "=r"((r)[11]), \
          "=r"((r)[12]), "=r"((r)[13]), "=r"((r)[14]), "=r"((r)[15]), \
          "=r"((r)[16]), "=r"((r)[17]), "=r"((r)[18]), "=r"((r)[19]), \
          "=r"((r)[20]), "=r"((r)[21]), "=r"((r)[22]), "=r"((r)[23]), \
          "=r"((r)[24]), "=r"((r)[25]), "=r"((r)[26]), "=r"((r)[27]), \
          "=r"((r)[28]), "=r"((r)[29]), "=r"((r)[30]), "=r"((r)[31]) \
        : "r"(addr))
#define TC_ST_X32(addr, r) \
    asm volatile( \
        "tcgen05.st.sync.aligned.32x32b.x32.b32 [%0], " \
        "{%1, %2, %3, %4, %5, %6, %7, %8, " \
        " %9, %10, %11, %12, %13, %14, %15, %16, " \
        " %17, %18, %19, %20, %21, %22, %23, %24, " \
        " %25, %26, %27, %28, %29, %30, %31, %32};" \
        :: "r"(addr), \
           "r"((r)[0]),  "r"((r)[1]),  "r"((r)[2]),  "r"((r)[3]), \
           "r"((r)[4]),  "r"((r)[5]),  "r"((r)[6]),  "r"((r)[7]), \
           "r"((r)[8]),  "r"((r)[9]),  "r"((r)[10]), "r"((r)[11]), \
           "r"((r)[12]), "r"((r)[13]), "r"((r)[14]), "r"((r)[15]), \
           "r"((r)[16]), "r"((r)[17]), "r"((r)[18]), "r"((r)[19]), \
           "r"((r)[20]), "r"((r)[21]), "r"((r)[22]), "r"((r)[23]), \
           "r"((r)[24]), "r"((r)[25]), "r"((r)[26]), "r"((r)[27]), \
           "r"((r)[28]), "r"((r)[29]), "r"((r)[30]), "r"((r)[31]) \
        : "memory")
#endif

static __device__ __forceinline__ uint64_t make_desc(uint32_t addr) {
    const uint64_t base = (2ull << 61) | (1ull << 46) | (64ull << 32) | (1ull << 16);
    return base | ((uint64_t)(addr >> 4) & 0x3FFF);
}
static __device__ __forceinline__ uint32_t sw128(uint32_t off) {
    return off ^ ((off >> 3) & 0x70);
}
static __device__ __forceinline__ uint32_t pack_bf2(float a, float b) {
    __nv_bfloat162 t = __floats2bfloat162_rn(a, b);
    return *(uint32_t*)&t;
}

// ---------------------------------------------------------------------------
// Split pre-pass: hs -> g_as (slabs hi,hi,lo)
// ---------------------------------------------------------------------------
__global__ void split_hs_kernel(const float* __restrict__ hs)
{
    int i = blockIdx.x * 256 + threadIdx.x;     // over 4096*768
    float x = hs[i];
    __nv_bfloat16 h = __float2bfloat16(x);
    __nv_bfloat16 l = __float2bfloat16(x - __bfloat162float(h));
    int row = i / EMB, k = i - row * EMB;
    __nv_bfloat16* p = &g_as[(size_t)row * K2];
    p[k] = h; p[EMB + k] = h; p[2 * EMB + k] = l;
}

// Split + transpose weights: W_z[k][n] -> g_bs[z][n][slabs hi,lo,hi of k]
__global__ void split_w_kernel(const float* __restrict__ Wq,
                               const float* __restrict__ Wk,
                               const float* __restrict__ Wv)
{
    __shared__ float t[32][33];
    const int z = blockIdx.z;
    const float* W = (z == 0) ? Wq : (z == 1) ? Wk : Wv;
    int k = blockIdx.y * 32 + threadIdx.y;
    int n = blockIdx.x * 32 + threadIdx.x;
    t[threadIdx.y][threadIdx.x] = W[(size_t)k * EMB + n];
    __syncthreads();
    int nn = blockIdx.x * 32 + threadIdx.y;
    int kk = blockIdx.y * 32 + threadIdx.x;
    float x = t[threadIdx.x][threadIdx.y];
    __nv_bfloat16 h = __float2bfloat16(x);
    __nv_bfloat16 l = __float2bfloat16(x - __bfloat162float(h));
    __nv_bfloat16* p = &g_bs[((size_t)z * EMB + nn) * K2];
    p[kk] = h; p[EMB + kk] = l; p[2 * EMB + kk] = h;
}

// ---------------------------------------------------------------------------
// QKV GEMM on tcgen05 (validated R6).
// ---------------------------------------------------------------------------
#define STAGE_BYTES 49152
#define QKV_SMEM (2 * STAGE_BYTES + 32)
#define QKV_IDESC 0x8400490u              // f32 acc, bf16 a/b, N=256, M=128

__global__ __launch_bounds__(256) void qkv_mma_kernel(
    const float* __restrict__ bq, const float* __restrict__ bk,
    const float* __restrict__ bv)
{
    const int z = blockIdx.z;
    const float* bias = (z == 0) ? bq : (z == 1) ? bk : bv;
    float* dst = (z == 0) ? g_q : (z == 1) ? g_k : g_v;
    const int n0 = blockIdx.x * 256;
    const int m0 = blockIdx.y * 128;
    const int tid = threadIdx.x;

#if TC_OK
    extern __shared__ __align__(1024) char sm[];
    const uint32_t sb = smem_u32(sm);
    const int wid = tid >> 5, lid = tid & 31;

    const uint32_t ctrl = sb + 2 * STAGE_BYTES;
    const uint32_t mb[2] = { sb + 2 * STAGE_BYTES + 8, sb + 2 * STAGE_BYTES + 16 };

    if (tid == 0) { mbar_init(mb[0], 1); mbar_init(mb[1], 1); }
    if (wid == 0) {
        asm volatile("tcgen05.alloc.cta_group::1.sync.aligned.shared::cta.b32 [%0], %1;"
                     :: "r"(ctrl), "r"(256u) : "memory");
        asm volatile("tcgen05.relinquish_alloc_permit.cta_group::1.sync.aligned;");
    }
    __syncthreads();
    uint32_t tmem;
    asm volatile("ld.shared.b32 %0, [%1];" : "=r"(tmem) : "r"(ctrl));

    const __nv_bfloat16* Arow = &g_as[(size_t)m0 * K2];
    const __nv_bfloat16* Brow = &g_bs[((size_t)z * EMB + n0) * K2];

    int ph[2] = { 0, 0 };

    for (int c = 0; c < 36; c++) {
        const int s = c & 1;
        if (c >= 2) { mbar_wait(mb[s], ph[s]); ph[s] ^= 1; }
        const int kk = c * 64;
        char* stA = sm + s * STAGE_BYTES;
        char* stB = stA + 16384;

        #pragma unroll
        for (int j = 0; j < 4; j++) {
            int cid = tid + j * 256;
            int r = cid >> 3, c16 = cid & 7;
            uint32_t off = sw128((uint32_t)(r * 128 + c16 * 16));
            *(uint4*)(stA + off) = *(const uint4*)(Arow + (size_t)r * K2 + kk + c16 * 8);
        }
        #pragma unroll
        for (int j = 0; j < 8; j++) {
            int cid = tid + j * 256;
            int r = cid >> 3, c16 = cid & 7;
            uint32_t off = sw128((uint32_t)(r * 128 + c16 * 16));
            *(uint4*)(stB + off) = *(const uint4*)(Brow + (size_t)r * K2 + kk + c16 * 8);
        }
        asm volatile("fence.proxy.async.shared::cta;" ::: "memory");
        __syncthreads();

        if (wid == 0) {
            if (elect_one()) {
                uint64_t da = make_desc(sb + s * STAGE_BYTES);
                uint64_t db = make_desc(sb + s * STAGE_BYTES + 16384);
                #pragma unroll
                for (int k = 0; k < 4; k++)
                    mma_f16_ss(tmem, da + k * 2, db + k * 2, QKV_IDESC, (c > 0) || (k > 0));
                tc_commit(mb[s]);
            }
        }
    }

    mbar_wait(mb[1], ph[1]);
    asm volatile("tcgen05.fence::after_thread_sync;" ::: "memory");

    if (wid < 4) {
        const int r = wid * 32 + lid;
        const float scl = (z == 0) ? 0.125f : 1.0f;
        #pragma unroll
        for (int cb = 0; cb < 8; cb++) {
            uint32_t dr[32];
            TC_LD_X32(dr, tmem + cb * 32);
            asm volatile("tcgen05.wait::ld.sync.aligned;" ::: "memory");
            const int nbase = n0 + cb * 32;
            const int head = nbase >> 6;
            float* op = &dst[((size_t)head * SQ + m0 + r) * HD + (nbase & 63)];
            #pragma unroll
            for (int q = 0; q < 32; q += 4) {
                float4 v;
                v.x = (__uint_as_float(dr[q + 0]) + bias[nbase + q + 0]) * scl;
                v.y = (__uint_as_float(dr[q + 1]) + bias[nbase + q + 1]) * scl;
                v.z = (__uint_as_float(dr[q + 2]) + bias[nbase + q + 2]) * scl;
                v.w = (__uint_as_float(dr[q + 3]) + bias[nbase + q + 3]) * scl;
                *(float4*)&op[q] = v;
            }
        }
    }
    __syncthreads();
    if (wid == 0) {
        asm volatile("tcgen05.dealloc.cta_group::1.sync.aligned.b32 %0, %1;"
                     :: "r"(tmem), "r"(256u));
    }
#else
    const int r = tid >> 1;
    const int cb0 = (tid & 1) * 128;
    const float scl = (z == 0) ? 0.125f : 1.0f;
    const __nv_bfloat16* a = &g_as[(size_t)(m0 + r) * K2];
    for (int cc = 0; cc < 128; cc++) {
        const int n = n0 + cb0 + cc;
        const __nv_bfloat16* b = &g_bs[((size_t)z * EMB + n) * K2];
        float acc = 0.0f;
        for (int k = 0; k < K2; k++)
            acc += __bfloat162float(a[k]) * __bfloat162float(b[k]);
        const int head = n >> 6;
        dst[((size_t)head * SQ + m0 + r) * HD + (n & 63)] = (acc + bias[n]) * scl;
    }
#endif
}

// ---------------------------------------------------------------------------
// Banded attention on tcgen05: per CTA = (head, 128 queries), block = 128.
// S (M=128,N=64,K=64) and P.V (M=128,N=64,K=64) as 3-term bf16 hi/lo split
// MMAs; softmax thread-local (one query row per thread via LDTM); O lives in
// TMEM with LDTM/STTM online rescale.
// ---------------------------------------------------------------------------
#define AT_QHI   0
#define AT_QLO   16384
#define AT_KHI   32768
#define AT_KLO   40960
#define AT_VTHI  49152
#define AT_VTLO  57344
#define AT_PHI   65536
#define AT_PLO   81920
#define AT_VSTG  65536      // fp32 V stage [64][65] — unioned with P region
#define AT_KMSK  98304
#define AT_CTRL  98560
#define AT_MBAR  98568
#define AT_SMEM  98624
#define ATT_IDESC 0x8100490u   // f32 acc, bf16 a/b, N=64, M=128
#define TM_S 0
#define TM_O 64

__global__ __launch_bounds__(128) void attn_mma_kernel(
    const float* __restrict__ amask,
    const unsigned char* __restrict__ qmask,
    float* __restrict__ out)
{
    const int h  = blockIdx.y;
    const int q0 = blockIdx.x * 128;
    const int tid = threadIdx.x;

#if TC_OK
    extern __shared__ __align__(1024) char sm[];
    const uint32_t sb = smem_u32(sm);
    const int wid = tid >> 5;
    const uint32_t mb = sb + AT_MBAR;
    float* kmsk = (float*)(sm + AT_KMSK);
    float* vstg = (float*)(sm + AT_VSTG);   // [64][65]

    if (tid == 0) mbar_init(mb, 1);
    if (wid == 0) {
        asm volatile("tcgen05.alloc.cta_group::1.sync.aligned.shared::cta.b32 [%0], %1;"
                     :: "r"(sb + AT_CTRL), "r"(128u) : "memory");
        asm volatile("tcgen05.relinquish_alloc_permit.cta_group::1.sync.aligned;");
    }
    __syncthreads();
    uint32_t tmem;
    asm volatile("ld.shared.b32 %0, [%1];" : "=r"(tmem) : "r"(sb + AT_CTRL));
    const uint32_t st_off = (uint32_t)wid << 21;   // subpartition select for STTM

    // ---- Prologue: Q tile (128x64) -> Qhi/Qlo bf16, SW128-swizzled ----
    {
        const float* qp = &g_q[((size_t)h * SQ + q0 + tid) * HD];
        float f[64];
        #pragma unroll
        for (int i = 0; i < 16; i++) *(float4*)&f[i * 4] = *(const float4*)&qp[i * 4];
        #pragma unroll
        for (int g = 0; g < 8; g++) {
            uint32_t off = sw128((uint32_t)(tid * 128 + g * 16));
            uint4 hv, lv;
            float hi[8], lo[8];
            #pragma unroll
            for (int e = 0; e < 8; e++) {
                float x = f[g * 8 + e];
                __nv_bfloat16 hb = __float2bfloat16(x);
                hi[e] = __bfloat162float(hb);
                lo[e] = x - hi[e];
            }
            hv.x = pack_bf2(hi[0], hi[1]); hv.y = pack_bf2(hi[2], hi[3]);
            hv.z = pack_bf2(hi[4], hi[5]); hv.w = pack_bf2(hi[6], hi[7]);
            lv.x = pack_bf2(lo[0], lo[1]); lv.y = pack_bf2(lo[2], lo[3]);
            lv.z = pack_bf2(lo[4], lo[5]); lv.w = pack_bf2(lo[6], lo[7]);
            *(uint4*)(sm + AT_QHI + off) = hv;
            *(uint4*)(sm + AT_QLO + off) = lv;
        }
    }

    const int gi = q0 + tid;       // this thread's query row
    float m_i = -1e30f, l_i = 0.0f;
    int ph = 0;
    bool first = true;

    const uint64_t dQh = make_desc(sb + AT_QHI), dQl = make_desc(sb + AT_QLO);
    const uint64_t dKh = make_desc(sb + AT_KHI), dKl = make_desc(sb + AT_KLO);
    const uint64_t dVh = make_desc(sb + AT_VTHI), dVl = make_desc(sb + AT_VTLO);
    const uint64_t dPh = make_desc(sb + AT_PHI), dPl = make_desc(sb + AT_PLO);

    for (int t = 0; t < 10; t++) {
        const int jb = q0 - 256 + t * 64;
        if (jb < 0 || jb >= SQ) continue;

        __syncthreads();   // everyone done with K/V/P smem from prior tile

        // ---- Load K tile -> Khi/Klo (swizzled); V tile -> fp32 stage ----
        {
            const int rk = tid >> 1, half = (tid & 1) * 32;
            const float* kp = &g_k[((size_t)h * SQ + jb + rk) * HD + half];
            const float* vp = &g_v[((size_t)h * SQ + jb + rk) * HD + half];
            float f[32];
            #pragma unroll
            for (int i = 0; i < 8; i++) *(float4*)&f[i * 4] = *(const float4*)&kp[i * 4];
            #pragma unroll
            for (int g = 0; g < 4; g++) {
                uint32_t off = sw128((uint32_t)(rk * 128 + half * 2 + g * 16));
                uint4 hv, lv;
                float hi[8], lo[8];
                #pragma unroll
                for (int e = 0; e < 8; e++) {
                    float x = f[g * 8 + e];
                    __nv_bfloat16 hb = __float2bfloat16(x);
                    hi[e] = __bfloat162float(hb);
                    lo[e] = x - hi[e];
                }
                hv.x = pack_bf2(hi[0], hi[1]); hv.y = pack_bf2(hi[2], hi[3]);
                hv.z = pack_bf2(hi[4], hi[5]); hv.w = pack_bf2(hi[6], hi[7]);
                lv.x = pack_bf2(lo[0], lo[1]); lv.y = pack_bf2(lo[2], lo[3]);
                lv.z = pack_bf2(lo[4], lo[5]); lv.w = pack_bf2(lo[6], lo[7]);
                *(uint4*)(sm + AT_KHI + off) = hv;
                *(uint4*)(sm + AT_KLO + off) = lv;
            }
            #pragma unroll
            for (int i = 0; i < 32; i++) vstg[rk * 65 + half + i] = vp[i];
            if (tid < 64)
                kmsk[tid] = (amask[jb + tid] != 0.0f) ? -1e8f : 0.0f;
        }
        __syncthreads();

        // ---- Transpose V stage -> Vthi/Vtlo [dim][key] (swizzled) ----
        {
            const int d = tid & 63, kh = (tid >> 6) * 32;
            float f[32];
            #pragma unroll
            for (int i = 0; i < 32; i++) f[i] = vstg[(kh + i) * 65 + d];
            #pragma unroll
            for (int g = 0; g < 4; g++) {
                uint32_t off = sw128((uint32_t)(d * 128 + kh * 2 + g * 16));
                uint4 hv, lv;
                float hi[8], lo[8];
                #pragma unroll
                for (int e = 0; e < 8; e++) {
                    float x = f[g * 8 + e];
                    __nv_bfloat16 hb = __float2bfloat16(x);
                    hi[e] = __bfloat162float(hb);
                    lo[e] = x - hi[e];
                }
                hv.x = pack_bf2(hi[0], hi[1]); hv.y = pack_bf2(hi[2], hi[3]);
                hv.z = pack_bf2(hi[4], hi[5]); hv.w = pack_bf2(hi[6], hi[7]);
                lv.x = pack_bf2(lo[0], lo[1]); lv.y = pack_bf2(lo[2], lo[3]);
                lv.z = pack_bf2(lo[4], lo[5]); lv.w = pack_bf2(lo[6], lo[7]);
                *(uint4*)(sm + AT_VTHI + off) = hv;
                *(uint4*)(sm + AT_VTLO + off) = lv;
            }
        }
        asm volatile("fence.proxy.async.shared::cta;" ::: "memory");
        __syncthreads();

        // ---- S = Q.K^T (3-term split), commit, wait ----
        if (wid == 0 && elect_one()) {
            asm volatile("tcgen05.fence::after_thread_sync;" ::: "memory");
            #pragma unroll
            for (int k = 0; k < 4; k++) mma_f16_ss(tmem + TM_S, dQh + k * 2, dKh + k * 2, ATT_IDESC, k > 0);
            #pragma unroll
            for (int k = 0; k < 4; k++) mma_f16_ss(tmem + TM_S, dQh + k * 2, dKl + k * 2, ATT_IDESC, true);
            #pragma unroll
            for (int k = 0; k < 4; k++) mma_f16_ss(tmem + TM_S, dQl + k * 2, dKh + k * 2, ATT_IDESC, true);
            tc_commit(mb);
        }
        mbar_wait(mb, ph); ph ^= 1;
        asm volatile("tcgen05.fence::after_thread_sync;" ::: "memory");

        // ---- Softmax (thread-local row) ----
        uint32_t s0[32], s1[32];
        TC_LD_X32(s0, tmem + TM_S);
        TC_LD_X32(s1, tmem + TM_S + 32);
        asm volatile("tcgen05.wait::ld.sync.aligned;" ::: "memory");

        float p[64];
        float rowm = -1e30f;
        #pragma unroll
        for (int j = 0; j < 64; j++) {
            const int gj = jb + j;
            const int diff = gi - gj;
            const bool valid = (diff <= WIN) && (diff >= -WIN);
            float sv = __uint_as_float(j < 32 ? s0[j] : s1[j - 32]) + kmsk[j];
            p[j] = valid ? sv : -1e30f;
            if (valid) rowm = fmaxf(rowm, sv);
        }
        const float newm = fmaxf(m_i, rowm);
        const float rsc = __expf(m_i - newm);
        m_i = newm;
        float rs = 0.0f;
        #pragma unroll
        for (int j = 0; j < 64; j++) {
            float pv = (p[j] > -1e29f) ? __expf(p[j] - newm) : 0.0f;
            p[j] = pv;
            rs += pv;
        }
        l_i = l_i * rsc + rs;

        // ---- Store P (hi/lo split) into smem A-tile ----
        #pragma unroll
        for (int g = 0; g < 8; g++) {
            uint32_t off = sw128((uint32_t)(tid * 128 + g * 16));
            uint4 hv, lv;
            float hi[8], lo[8];
            #pragma unroll
            for (int e = 0; e < 8; e++) {
                float x = p[g * 8 + e];
                __nv_bfloat16 hb = __float2bfloat16(x);
                hi[e] = __bfloat162float(hb);
                lo[e] = x - hi[e];
            }
            hv.x = pack_bf2(hi[0], hi[1]); hv.y = pack_bf2(hi[2], hi[3]);
            hv.z = pack_bf2(hi[4], hi[5]); hv.w = pack_bf2(hi[6], hi[7]);
            lv.x = pack_bf2(lo[0], lo[1]); lv.y = pack_bf2(lo[2], lo[3]);
            lv.z = pack_bf2(lo[4], lo[5]); lv.w = pack_bf2(lo[6], lo[7]);
            *(uint4*)(sm + AT_PHI + off) = hv;
            *(uint4*)(sm + AT_PLO + off) = lv;
        }

        // ---- Rescale O in TMEM (skip on first contributing tile) ----
        if (!first) {
            uint32_t o0[32], o1[32];
            TC_LD_X32(o0, tmem + TM_O);
            TC_LD_X32(o1, tmem + TM_O + 32);
            asm volatile("tcgen05.wait::ld.sync.aligned;" ::: "memory");
            #pragma unroll
            for (int j = 0; j < 32; j++) {
                o0[j] = __float_as_uint(__uint_as_float(o0[j]) * rsc);
                o1[j] = __float_as_uint(__uint_as_float(o1[j]) * rsc);
            }
            TC_ST_X32(tmem + TM_O + st_off, o0);
            TC_ST_X32(tmem + TM_O + 32 + st_off, o1);
            asm volatile("tcgen05.wait::st.sync.aligned;" ::: "memory");
        }
        asm volatile("tcgen05.fence::before_thread_sync;" ::: "memory");
        asm volatile("fence.proxy.async.shared::cta;" ::: "memory");
        __syncthreads();

        // ---- O += P.V (3-term split), commit, wait ----
        if (wid == 0 && elect_one()) {
            asm volatile("tcgen05.fence::after_thread_sync;" ::: "memory");
            #pragma unroll
            for (int k = 0; k < 4; k++) mma_f16_ss(tmem + TM_O, dPh + k * 2, dVh + k * 2, ATT_IDESC, !(first && k == 0));
            #pragma unroll
            for (int k = 0; k < 4; k++) mma_f16_ss(tmem + TM_O, dPh + k * 2, dVl + k * 2, ATT_IDESC, true);
            #pragma unroll
            for (int k = 0; k < 4; k++) mma_f16_ss(tmem + TM_O, dPl + k * 2, dVh + k * 2, ATT_IDESC, true);
            tc_commit(mb);
        }
        mbar_wait(mb, ph); ph ^= 1;
        first = false;
    }

    // ---- Epilogue: O / l, is_index_masked, write out ----
    asm volatile("tcgen05.fence::after_thread_sync;" ::: "memory");
    {
        uint32_t o0[32], o1[32];
        TC_LD_X32(o0, tmem + TM_O);
        TC_LD_X32(o1, tmem + TM_O + 32);
        asm volatile("tcgen05.wait::ld.sync.aligned;" ::: "memory");
        const float inv = (qmask[gi] != 0) ? 0.0f : 1.0f / l_i;
        float* op = &out[(size_t)gi * EMB + h * HD];
        #pragma unroll
        for (int j = 0; j < 32; j += 4) {
            float4 v;
            v.x = __uint_as_float(o0[j + 0]) * inv;
            v.y = __uint_as_float(o0[j + 1]) * inv;
            v.z = __uint_as_float(o0[j + 2]) * inv;
            v.w = __uint_as_float(o0[j + 3]) * inv;
            *(float4*)&op[j] = v;
            v.x = __uint_as_float(o1[j + 0]) * inv;
            v.y = __uint_as_float(o1[j + 1]) * inv;
            v.z = __uint_as_float(o1[j + 2]) * inv;
            v.w = __uint_as_float(o1[j + 3]) * inv;
            *(float4*)&op[32 + j] = v;
        }
    }
    __syncthreads();
    if (wid == 0) {
        asm volatile("tcgen05.dealloc.cta_group::1.sync.aligned.b32 %0, %1;"
                     :: "r"(tmem), "r"(128u));
    }
#else
    // Generic fallback (compute_103 PTX pass only; never runs on GB300).
    const int gi = q0 + tid;
    const float* qp = &g_q[((size_t)h * SQ + gi) * HD];
    float m = -1e30f, l = 0.0f, O[64];
    #pragma unroll
    for (int d = 0; d < 64; d++) O[d] = 0.0f;
    int lo = gi - WIN; if (lo < 0) lo = 0;
    int hi = gi + WIN; if (hi > SQ - 1) hi = SQ - 1;
    for (int gj = lo; gj <= hi; gj++) {
        const float* kp = &g_k[((size_t)h * SQ + gj) * HD];
        float s = 0.0f;
        for (int d = 0; d < 64; d++) s += qp[d] * kp[d];
        s += (amask[gj] != 0.0f) ? -1e8f : 0.0f;
        float nm = fmaxf(m, s);
        float r = __expf(m - nm);
        float pv = __expf(s - nm);
        m = nm; l = l * r + pv;
        const float* vp = &g_v[((size_t)h * SQ + gj) * HD];
        for (int d = 0; d < 64; d++) O[d] = O[d] * r + pv * vp[d];
    }
    const float inv = (qmask[gi] != 0) ? 0.0f : 1.0f / l;
    float* op = &out[(size_t)gi * EMB + h * HD];
    for (int d = 0; d < 64; d++) op[d] = O[d] * inv;
#endif
}

// ---------------------------------------------------------------------------
// Launch
// ---------------------------------------------------------------------------
extern "C" void kernel_launch(void* const* d_in, const int* in_sizes, int n_in,
                              void* d_out, int out_size)
{
    const float* hs            = (const float*)d_in[0];
    const float* amask         = (const float*)d_in[1];
    const unsigned char* qmask = (const unsigned char*)d_in[2];
    const float* Wq = (const float*)d_in[3];
    const float* bq = (const float*)d_in[4];
    const float* Wk = (const float*)d_in[5];
    const float* bk = (const float*)d_in[6];
    const float* Wv = (const float*)d_in[7];
    const float* bv = (const float*)d_in[8];
    float* out = (float*)d_out;

    split_hs_kernel<<<(SQ * EMB) / 256, 256>>>(hs);
    split_w_kernel<<<dim3(EMB / 32, EMB / 32, 3), dim3(32, 32)>>>(Wq, Wk, Wv);

    cudaFuncSetAttribute(qkv_mma_kernel,
                         cudaFuncAttributeMaxDynamicSharedMemorySize, QKV_SMEM);
    qkv_mma_kernel<<<dim3(EMB / 256, SQ / 128, 3), 256, QKV_SMEM>>>(bq, bk, bv);

    cudaFuncSetAttribute(attn_mma_kernel,
                         cudaFuncAttributeMaxDynamicSharedMemorySize, AT_SMEM);
    attn_mma_kernel<<<dim3(SQ / 128, NH), 128, AT_SMEM>>>(amask, qmask, out);
}